// round 14
// baseline (speedup 1.0000x reference)
#include <cuda_runtime.h>
#include <cuda_fp16.h>
#include <math.h>
#include <float.h>
#include <stdint.h>

// Problem dims
#define B_ 2
#define S_ 2048
#define H_ 16
#define D_ 128
#define E_ 2048
#define M_ (B_*S_)   // 4096 tokens

// fp16 operands (all single-rn)
__device__ __half g_Xh[M_*E_];       // X single fp16
__device__ __half g_Wh[4*E_*E_];     // (q,k,v,o) single fp16
__device__ __half g_Ah[M_*E_];       // attention output single fp16 [B,S,E]
// post-RoPE QKV in [B,H,S,D], single fp16 (Q pre-scaled by 1/sqrt(D))
__device__ __half g_Qh[B_*H_*S_*D_];
__device__ __half g_Kh[B_*H_*S_*D_];
__device__ __half g_Vh[B_*H_*S_*D_];
// RoPE tables [pos][i] for i in 0..63
__device__ float g_cos[S_*64];
__device__ float g_sin[S_*64];

#define ASCALE 0.088388347648318447f   // 1/sqrt(128), folded into Q
#define LOG2E  1.4426950408889634f

__device__ __forceinline__ uint32_t smem_to_u32(const void* smem_ptr) {
    uint32_t addr;
    asm("{ .reg .u64 tmp; cvta.to.shared.u64 tmp, %1; cvt.u32.u64 %0, tmp; }"
        : "=r"(addr) : "l"(smem_ptr));
    return addr;
}

#define CP_ASYNC16(dst, src) \
    asm volatile("cp.async.cg.shared.global [%0], [%1], 16;" \
        :: "r"(dst), "l"(src) : "memory")
#define CP_ASYNC_COMMIT() asm volatile("cp.async.commit_group;" ::: "memory")
#define CP_ASYNC_WAIT0()  asm volatile("cp.async.wait_group 0;" ::: "memory")

__device__ __forceinline__ void ldsm_x4(uint32_t* r, uint32_t addr) {
    asm volatile("ldmatrix.sync.aligned.m8n8.x4.shared.b16 {%0,%1,%2,%3}, [%4];"
        : "=r"(r[0]), "=r"(r[1]), "=r"(r[2]), "=r"(r[3]) : "r"(addr));
}
__device__ __forceinline__ void ldsm_x4_trans(uint32_t* r, uint32_t addr) {
    asm volatile("ldmatrix.sync.aligned.m8n8.x4.trans.shared.b16 {%0,%1,%2,%3}, [%4];"
        : "=r"(r[0]), "=r"(r[1]), "=r"(r[2]), "=r"(r[3]) : "r"(addr));
}

__device__ __forceinline__ void mma16816(float* c, const uint32_t* a,
                                          uint32_t b0, uint32_t b1) {
    asm volatile(
        "mma.sync.aligned.m16n8k16.row.col.f32.f16.f16.f32 "
        "{%0,%1,%2,%3}, {%4,%5,%6,%7}, {%8,%9}, {%0,%1,%2,%3};"
        : "+f"(c[0]), "+f"(c[1]), "+f"(c[2]), "+f"(c[3])
        : "r"(a[0]), "r"(a[1]), "r"(a[2]), "r"(a[3]), "r"(b0), "r"(b1));
}

__device__ __forceinline__ uint32_t pack_f16(float a, float b) {
    __half2 p = __halves2half2(__float2half_rn(a), __float2half_rn(b));
    return *(uint32_t*)&p;
}

// ---------------------------------------------------------------------------
// Merged prologue: X + 4 weights -> fp16 rn (64B per thread), + RoPE table.
// Quad base (4k) never straddles a region boundary (all multiples of 4).
// ---------------------------------------------------------------------------
#define NX4 (M_*E_/4)    // 2^21
#define NW4 (E_*E_/4)    // 2^20
#define NCONV (NX4 + 4*NW4)
#define NCONV4 (NCONV/4)
#define NTAB (S_*64)

__global__ __launch_bounds__(256) void prologue_kernel(
    const float* __restrict__ X,
    const float* __restrict__ Wq, const float* __restrict__ Wk,
    const float* __restrict__ Wv, const float* __restrict__ Wo)
{
    int idx = blockIdx.x * 256 + threadIdx.x;
    if (idx < NCONV4) {
        int e = idx << 2;   // quad base
        const float* src;
        __half* dst;
        int off;
        if (e < NX4) {
            src = X; dst = g_Xh; off = e;
        } else {
            int t = e - NX4;
            int slot = t >> 20;
            off = t & (NW4 - 1);
            src = (slot == 0) ? Wq : (slot == 1) ? Wk : (slot == 2) ? Wv : Wo;
            dst = g_Wh + (size_t)slot * E_ * E_;
        }
        float4 v0 = ((const float4*)src)[off];
        float4 v1 = ((const float4*)src)[off + 1];
        float4 v2 = ((const float4*)src)[off + 2];
        float4 v3 = ((const float4*)src)[off + 3];
        uint4 h0, h1;
        h0.x = pack_f16(v0.x, v0.y); h0.y = pack_f16(v0.z, v0.w);
        h0.z = pack_f16(v1.x, v1.y); h0.w = pack_f16(v1.z, v1.w);
        h1.x = pack_f16(v2.x, v2.y); h1.y = pack_f16(v2.z, v2.w);
        h1.z = pack_f16(v3.x, v3.y); h1.w = pack_f16(v3.z, v3.w);
        ((uint4*)dst)[(off >> 1) + 0] = h0;
        ((uint4*)dst)[(off >> 1) + 1] = h1;
    } else {
        int t = idx - NCONV4;
        if (t < NTAB) {
            int p = t >> 6;
            int i = t & 63;
            float inv = powf(10000.0f, -(float)(2 * i) / 128.0f);
            float sn, cs;
            sincosf((float)p * inv, &sn, &cs);
            g_cos[t] = cs;
            g_sin[t] = sn;
        }
    }
}

// ---------------------------------------------------------------------------
// fp16 single-term GEMM: C[m,n] = sum_k A[m,k] * W[n,k]
// Warp tile 16x128 (M-only warp split): each warp owns ALL 128 columns for
// its 16 rows, so the RoPE pair (i, i+64) lives in one thread -> register
// RoPE epilogue, no smem staging.
// MODE 0: qkv (A = Xh), fused RoPE epilogue (Q pre-scaled by 1/sqrt(D)).
// MODE 1: oproj (A = g_Ah), writes fp32 out.
// Block tile 128x128, 8 warps, K-chunk 64, 2-stage, 2 CTAs/SM.
// ---------------------------------------------------------------------------
#define KCH 64
#define NKC (E_/KCH)          // 32
#define ROWB 144              // 64 fp16 = 128B + 16B pad
#define TILE_B (128*ROWB)     // 18432
#define STG_B  (2*TILE_B)     // 36864: Ah, Bh
#define GEMM_SMEM 73728

template<int MODE>
__global__ __launch_bounds__(256, 2) void gemm_mma(
    float* __restrict__ Oout, const int* __restrict__ posids)
{
    extern __shared__ char gsm[];
    const uint32_t sb = smem_to_u32(gsm);

    const int tid  = threadIdx.x;
    const int lane = tid & 31;
    const int warp = tid >> 5;          // 0..7 -> 16 rows each
    const int m0 = blockIdx.y * 128;
    const int n0 = blockIdx.x * 128;
    const int z  = (MODE == 0) ? blockIdx.z : 3;

    const __half* Ahg = (MODE == 0) ? g_Xh : g_Ah;
    const __half* Bhg = g_Wh + (size_t)z * E_ * E_;

    const int lrow = tid >> 3;          // 0..31 (row base, +32 per it)
    const int lp   = tid & 7;           // 16B chunk within 128B row

    float c[16][4];
#pragma unroll
    for (int j = 0; j < 16; j++)
#pragma unroll
        for (int q = 0; q < 4; q++) c[j][q] = 0.f;

    const uint32_t aRow = (uint32_t)(warp * 16 + (lane & 15)) * ROWB
                        + (uint32_t)(lane >> 4) * 16;
    const uint32_t bRow = (uint32_t)((lane & 7) + ((lane >> 4) << 3)) * ROWB
                        + (uint32_t)((lane >> 3) & 1) * 16;

    auto load_stage = [&](int buf, int kc) {
        const uint32_t stg = sb + buf * STG_B;
#pragma unroll
        for (int it = 0; it < 4; it++) {
            int row = lrow + it * 32;
            const size_t gA = (size_t)(m0 + row) * E_ + kc * KCH + lp * 8;
            const size_t gB = (size_t)(n0 + row) * E_ + kc * KCH + lp * 8;
            const uint32_t so = (uint32_t)(row * ROWB + lp * 16);
            CP_ASYNC16(stg + 0 * TILE_B + so, Ahg + gA);
            CP_ASYNC16(stg + 1 * TILE_B + so, Bhg + gB);
        }
        CP_ASYNC_COMMIT();
    };

    load_stage(0, 0);

    for (int kc = 0; kc < NKC; kc++) {
        const int buf = kc & 1;
        CP_ASYNC_WAIT0();
        __syncthreads();
        if (kc + 1 < NKC) load_stage(buf ^ 1, kc + 1);

        const uint32_t stg = sb + buf * STG_B;
#pragma unroll
        for (int ks = 0; ks < 4; ks++) {
            uint32_t ah[4];
            ldsm_x4(ah, stg + 0 * TILE_B + aRow + (uint32_t)ks * 32);
#pragma unroll
            for (int g = 0; g < 8; g++) {
                uint32_t bh[4];
                ldsm_x4(bh, stg + 1 * TILE_B + bRow
                            + (uint32_t)g * 16 * ROWB + (uint32_t)ks * 32);
                mma16816(c[2 * g],     ah, bh[0], bh[1]);
                mma16816(c[2 * g + 1], ah, bh[2], bh[3]);
            }
        }
        __syncthreads();
    }

    const int rr = lane >> 2;
    const int ct = 2 * (lane & 3);
    const int row0 = m0 + warp * 16 + rr;
    const int row1 = row0 + 8;

    if (MODE == 1) {
#pragma unroll
        for (int ni = 0; ni < 16; ni++) {
            int col = n0 + ni * 8 + ct;
            *(float2*)&Oout[(size_t)row0 * E_ + col] =
                make_float2(c[ni][0], c[ni][1]);
            *(float2*)&Oout[(size_t)row1 * E_ + col] =
                make_float2(c[ni][2], c[ni][3]);
        }
        return;
    }

    // ---- MODE 0 register RoPE epilogue ----
    const int headi = n0 >> 7;
    __half* Out = (z == 0) ? g_Qh : (z == 1) ? g_Kh : g_Vh;
    const float qsc = (z == 0) ? ASCALE : 1.0f;

#pragma unroll
    for (int rsel = 0; rsel < 2; rsel++) {
        const int m = (rsel == 0) ? row0 : row1;
        const int q0 = 2 * rsel;                 // accumulator pair offset
        const int bb = m >> 11, ss = m & (S_ - 1);
        const size_t gbase = (((size_t)(bb * H_ + headi)) * S_ + ss) * D_;
        if (z < 2) {
            const int p = posids[bb * S_ + ss];
#pragma unroll
            for (int ni = 0; ni < 8; ni++) {
                const int i2 = ni * 8 + ct;              // 0..62, even
                float2 cs2 = *(float2*)&g_cos[p * 64 + i2];
                float2 sn2 = *(float2*)&g_sin[p * 64 + i2];
                float xl0 = c[ni][q0],     xl1 = c[ni][q0 + 1];
                float xh0 = c[ni + 8][q0], xh1 = c[ni + 8][q0 + 1];
                float o1x = (xl0 * cs2.x - xh0 * sn2.x) * qsc;
                float o1y = (xl1 * cs2.y - xh1 * sn2.y) * qsc;
                float o2x = (xh0 * cs2.x + xl0 * sn2.x) * qsc;
                float o2y = (xh1 * cs2.y + xl1 * sn2.y) * qsc;
                *(uint32_t*)&Out[gbase + i2]      = pack_f16(o1x, o1y);
                *(uint32_t*)&Out[gbase + 64 + i2] = pack_f16(o2x, o2y);
            }
        } else {
#pragma unroll
            for (int ni = 0; ni < 8; ni++) {
                const int i2 = ni * 8 + ct;
                *(uint32_t*)&Out[gbase + i2] =
                    pack_f16(c[ni][q0], c[ni][q0 + 1]);
                *(uint32_t*)&Out[gbase + 64 + i2] =
                    pack_f16(c[ni + 8][q0], c[ni + 8][q0 + 1]);
            }
        }
    }
}

// ---------------------------------------------------------------------------
// Causal flash attention, fp16 single-term (unchanged from round 13).
// block = (qt, h, b); 8 warps (256 threads). BQ=128, BK=64, D=128.
// qt reversed so longest CTAs launch first. 2 CTAs/SM (smem 104448).
// ---------------------------------------------------------------------------
#define AROW 272                 // 128 fp16 = 256B + 16B pad
#define QTILE_B (128*AROW)       // 34816
#define KVTILE  (64*AROW)        // 17408
#define AQ_H 0
#define KV_BASE QTILE_B          // 34816
#define KVSTG (2*KVTILE)         // KH, VH = 34816
#define KV_KH 0
#define KV_VH KVTILE
#define ATTN_SMEM (KV_BASE + 2*KVSTG)  // 104448 -> 2 CTAs/SM

__global__ __launch_bounds__(256, 2) void attn_mma()
{
    const int qt = (int)(gridDim.x - 1 - blockIdx.x);   // long CTAs first
    const int h  = blockIdx.y;
    const int b  = blockIdx.z;

    extern __shared__ char asm_[];
    const uint32_t sb = smem_to_u32(asm_);

    const int tid  = threadIdx.x;
    const int lane = tid & 31;
    const int warp = tid >> 5;

    const size_t headoff = (((size_t)(b * H_ + h)) * S_) * D_;
    const __half* Qh = g_Qh + headoff;
    const __half* Kh = g_Kh + headoff;
    const __half* Vh = g_Vh + headoff;

    // Q tile: 128 x 128 fp16
#pragma unroll
    for (int it = 0; it < 8; it++) {
        int lin = it * 256 + tid;
        int row = lin >> 4;
        int ch  = lin & 15;
        const size_t src = (size_t)(qt * 128 + row) * D_ + ch * 8;
        uint32_t dst = (uint32_t)(row * AROW + ch * 16);
        CP_ASYNC16(sb + AQ_H + dst, Qh + src);
    }
    CP_ASYNC_COMMIT();

    auto load_kv = [&](int bufi, int kt) {
        const uint32_t stg = sb + KV_BASE + bufi * KVSTG;
#pragma unroll
        for (int it = 0; it < 4; it++) {
            int lin = it * 256 + tid;
            int row = lin >> 4;
            int ch  = lin & 15;
            const size_t src = (size_t)(kt * 64 + row) * D_ + ch * 8;
            uint32_t dst = (uint32_t)(row * AROW + ch * 16);
            CP_ASYNC16(stg + KV_KH + dst, Kh + src);
            CP_ASYNC16(stg + KV_VH + dst, Vh + src);
        }
        CP_ASYNC_COMMIT();
    };

    load_kv(0, 0);
    CP_ASYNC_WAIT0();
    __syncthreads();

    const uint32_t aRow = (uint32_t)(warp * 16 + (lane & 15)) * AROW
                        + (uint32_t)(lane >> 4) * 16;
    const uint32_t bRow = (uint32_t)((lane & 7) + ((lane >> 4) << 3)) * AROW
                        + (uint32_t)((lane >> 3) & 1) * 16;
    const uint32_t vRow = (uint32_t)(lane & 15) * AROW
                        + (uint32_t)(lane >> 4) * 16;

    float m0r = -INFINITY, m1r = -INFINITY, l0r = 0.f, l1r = 0.f;
    float co[16][4];
#pragma unroll
    for (int j = 0; j < 16; j++)
#pragma unroll
        for (int q = 0; q < 4; q++) co[j][q] = 0.f;

    const int qrow0 = qt * 128 + warp * 16 + (lane >> 2);
    const int qrow1 = qrow0 + 8;
    const int nkt = 2 * qt + 2;

    for (int kt = 0; kt < nkt; kt++) {
        const int bufi = kt & 1;
        if (kt + 1 < nkt) load_kv(bufi ^ 1, kt + 1);
        const uint32_t kvs = sb + KV_BASE + bufi * KVSTG;

        // --- S = Q K^T (single term), scores already scaled ---
        float s[8][4];
#pragma unroll
        for (int j = 0; j < 8; j++)
#pragma unroll
            for (int q = 0; q < 4; q++) s[j][q] = 0.f;

#pragma unroll
        for (int kd = 0; kd < 8; kd++) {
            uint32_t qh_[4];
            ldsm_x4(qh_, sb + AQ_H + aRow + kd * 32);
#pragma unroll
            for (int g = 0; g < 4; g++) {
                uint32_t kbh[4];
                uint32_t boff = bRow + (uint32_t)g * 16 * AROW + (uint32_t)kd * 32;
                ldsm_x4(kbh, kvs + KV_KH + boff);
#pragma unroll
                for (int hh = 0; hh < 2; hh++) {
                    mma16816(s[2 * g + hh], qh_, kbh[2 * hh], kbh[2 * hh + 1]);
                }
            }
        }

        // --- causal mask ---
        if (kt >= 2 * qt) {
            const int kbase = kt * 64 + 2 * (lane & 3);
#pragma unroll
            for (int j = 0; j < 8; j++) {
                int k0 = kbase + 8 * j;
                if (k0 > qrow0)     s[j][0] = -INFINITY;
                if (k0 + 1 > qrow0) s[j][1] = -INFINITY;
                if (k0 > qrow1)     s[j][2] = -INFINITY;
                if (k0 + 1 > qrow1) s[j][3] = -INFINITY;
            }
        }

        // --- online softmax (exp2 with log2e fold) ---
        float mx0 = s[0][0], mx1 = s[0][2];
#pragma unroll
        for (int j = 0; j < 8; j++) {
            mx0 = fmaxf(mx0, fmaxf(s[j][0], s[j][1]));
            mx1 = fmaxf(mx1, fmaxf(s[j][2], s[j][3]));
        }
        mx0 = fmaxf(mx0, __shfl_xor_sync(0xffffffffu, mx0, 1));
        mx0 = fmaxf(mx0, __shfl_xor_sync(0xffffffffu, mx0, 2));
        mx1 = fmaxf(mx1, __shfl_xor_sync(0xffffffffu, mx1, 1));
        mx1 = fmaxf(mx1, __shfl_xor_sync(0xffffffffu, mx1, 2));

        float mn0 = fmaxf(m0r, mx0), mn1 = fmaxf(m1r, mx1);
        float corr0 = exp2f((m0r - mn0) * LOG2E);
        float corr1 = exp2f((m1r - mn1) * LOG2E);
        m0r = mn0; m1r = mn1;
        const float b0 = mn0 * LOG2E;
        const float b1 = mn1 * LOG2E;

        float rs0 = 0.f, rs1 = 0.f;
#pragma unroll
        for (int j = 0; j < 8; j++) {
            s[j][0] = exp2f(fmaf(s[j][0], LOG2E, -b0));
            s[j][1] = exp2f(fmaf(s[j][1], LOG2E, -b0));
            s[j][2] = exp2f(fmaf(s[j][2], LOG2E, -b1));
            s[j][3] = exp2f(fmaf(s[j][3], LOG2E, -b1));
            rs0 += s[j][0] + s[j][1];
            rs1 += s[j][2] + s[j][3];
        }
        rs0 += __shfl_xor_sync(0xffffffffu, rs0, 1);
        rs0 += __shfl_xor_sync(0xffffffffu, rs0, 2);
        rs1 += __shfl_xor_sync(0xffffffffu, rs1, 1);
        rs1 += __shfl_xor_sync(0xffffffffu, rs1, 2);
        l0r = l0r * corr0 + rs0;
        l1r = l1r * corr1 + rs1;

#pragma unroll
        for (int j = 0; j < 16; j++) {
            co[j][0] *= corr0; co[j][1] *= corr0;
            co[j][2] *= corr1; co[j][3] *= corr1;
        }

        // --- O += P V (single term) ---
#pragma unroll
        for (int ks = 0; ks < 4; ks++) {
            float* cA = s[2 * ks];
            float* cB = s[2 * ks + 1];
            uint32_t ph[4];
            ph[0] = pack_f16(cA[0], cA[1]);
            ph[1] = pack_f16(cA[2], cA[3]);
            ph[2] = pack_f16(cB[0], cB[1]);
            ph[3] = pack_f16(cB[2], cB[3]);
#pragma unroll
            for (int dd = 0; dd < 8; dd++) {
                uint32_t vh_[4];
                uint32_t voff = vRow + (uint32_t)ks * 16 * AROW + (uint32_t)dd * 32;
                ldsm_x4_trans(vh_, kvs + KV_VH + voff);
                mma16816(co[2 * dd],     ph, vh_[0], vh_[1]);
                mma16816(co[2 * dd + 1], ph, vh_[2], vh_[3]);
            }
        }

        if (kt + 1 < nkt) CP_ASYNC_WAIT0();
        __syncthreads();
    }

    // --- epilogue: normalize, write A (single fp16) ---
    const float invl0 = 1.f / l0r;
    const float invl1 = 1.f / l1r;
    const int t2 = 2 * (lane & 3);
    const size_t rowA0 = ((size_t)(b * S_ + qrow0)) * E_ + h * D_;
    const size_t rowA1 = ((size_t)(b * S_ + qrow1)) * E_ + h * D_;
#pragma unroll
    for (int j = 0; j < 16; j++) {
        int col = 8 * j + t2;
        float a0 = co[j][0] * invl0, a1 = co[j][1] * invl0;
        float a2 = co[j][2] * invl1, a3 = co[j][3] * invl1;
        *(uint32_t*)&g_Ah[rowA0 + col] = pack_f16(a0, a1);
        *(uint32_t*)&g_Ah[rowA1 + col] = pack_f16(a2, a3);
    }
}

// ---------------------------------------------------------------------------
extern "C" void kernel_launch(void* const* d_in, const int* in_sizes, int n_in,
                              void* d_out, int out_size)
{
    const float* hidden = (const float*)d_in[0];
    const int*   posids = (const int*)d_in[2];
    const float* Wq     = (const float*)d_in[3];
    const float* Wk     = (const float*)d_in[4];
    const float* Wv     = (const float*)d_in[5];
    const float* Wo     = (const float*)d_in[6];
    float*       out    = (float*)d_out;

    cudaFuncSetAttribute(gemm_mma<0>,
                         cudaFuncAttributeMaxDynamicSharedMemorySize, GEMM_SMEM);
    cudaFuncSetAttribute(gemm_mma<1>,
                         cudaFuncAttributeMaxDynamicSharedMemorySize, GEMM_SMEM);
    cudaFuncSetAttribute(attn_mma,
                         cudaFuncAttributeMaxDynamicSharedMemorySize, ATTN_SMEM);

    // 1) merged prologue: fp16 converts (64B/thread) + RoPE table
    {
        int total = NCONV4 + NTAB;
        prologue_kernel<<<(total + 255) / 256, 256>>>(hidden, Wq, Wk, Wv, Wo);
    }
    // 2) QKV projections + register RoPE epilogue
    {
        dim3 grid(E_ / 128, M_ / 128, 3);
        gemm_mma<0><<<grid, 256, GEMM_SMEM>>>(nullptr, posids);
    }
    // 3) causal flash attention -> g_Ah
    {
        dim3 grid(S_ / 128, H_, B_);
        attn_mma<<<grid, 256, ATTN_SMEM>>>();
    }
    // 4) output projection -> d_out
    {
        dim3 grid(E_ / 128, M_ / 128);
        gemm_mma<1><<<grid, 256, GEMM_SMEM>>>(out, nullptr);
    }
}

// round 15
// speedup vs baseline: 1.0739x; 1.0739x over previous
#include <cuda_runtime.h>
#include <cuda_fp16.h>
#include <math.h>
#include <float.h>
#include <stdint.h>

// Problem dims
#define B_ 2
#define S_ 2048
#define H_ 16
#define D_ 128
#define E_ 2048
#define M_ (B_*S_)   // 4096 tokens

// fp16 operands (all single-rn)
__device__ __half g_Xh[M_*E_];       // X single fp16
__device__ __half g_Wh[4*E_*E_];     // (q,k,v,o) single fp16
__device__ __half g_Ah[M_*E_];       // attention output single fp16 [B,S,E]
// post-RoPE QKV in [B,H,S,D], single fp16 (Q pre-scaled by 1/sqrt(D))
__device__ __half g_Qh[B_*H_*S_*D_];
__device__ __half g_Kh[B_*H_*S_*D_];
__device__ __half g_Vh[B_*H_*S_*D_];
// RoPE tables [pos][i] for i in 0..63
__device__ float g_cos[S_*64];
__device__ float g_sin[S_*64];

#define ASCALE 0.088388347648318447f   // 1/sqrt(128), folded into Q
#define LOG2E  1.4426950408889634f

__device__ __forceinline__ uint32_t smem_to_u32(const void* smem_ptr) {
    uint32_t addr;
    asm("{ .reg .u64 tmp; cvta.to.shared.u64 tmp, %1; cvt.u32.u64 %0, tmp; }"
        : "=r"(addr) : "l"(smem_ptr));
    return addr;
}

#define CP_ASYNC16(dst, src) \
    asm volatile("cp.async.cg.shared.global [%0], [%1], 16;" \
        :: "r"(dst), "l"(src) : "memory")
#define CP_ASYNC_COMMIT() asm volatile("cp.async.commit_group;" ::: "memory")
#define CP_ASYNC_WAIT0()  asm volatile("cp.async.wait_group 0;" ::: "memory")

__device__ __forceinline__ void ldsm_x4(uint32_t* r, uint32_t addr) {
    asm volatile("ldmatrix.sync.aligned.m8n8.x4.shared.b16 {%0,%1,%2,%3}, [%4];"
        : "=r"(r[0]), "=r"(r[1]), "=r"(r[2]), "=r"(r[3]) : "r"(addr));
}
__device__ __forceinline__ void ldsm_x4_trans(uint32_t* r, uint32_t addr) {
    asm volatile("ldmatrix.sync.aligned.m8n8.x4.trans.shared.b16 {%0,%1,%2,%3}, [%4];"
        : "=r"(r[0]), "=r"(r[1]), "=r"(r[2]), "=r"(r[3]) : "r"(addr));
}

__device__ __forceinline__ void mma16816(float* c, const uint32_t* a,
                                          uint32_t b0, uint32_t b1) {
    asm volatile(
        "mma.sync.aligned.m16n8k16.row.col.f32.f16.f16.f32 "
        "{%0,%1,%2,%3}, {%4,%5,%6,%7}, {%8,%9}, {%0,%1,%2,%3};"
        : "+f"(c[0]), "+f"(c[1]), "+f"(c[2]), "+f"(c[3])
        : "r"(a[0]), "r"(a[1]), "r"(a[2]), "r"(a[3]), "r"(b0), "r"(b1));
}

__device__ __forceinline__ uint32_t pack_f16(float a, float b) {
    __half2 p = __halves2half2(__float2half_rn(a), __float2half_rn(b));
    return *(uint32_t*)&p;
}

// ---------------------------------------------------------------------------
// Merged prologue: X + 4 weights -> fp16 rn (64B per thread), + RoPE table.
// Quad base (4k) never straddles a region boundary (all multiples of 4).
// ---------------------------------------------------------------------------
#define NX4 (M_*E_/4)    // 2^21
#define NW4 (E_*E_/4)    // 2^20
#define NCONV (NX4 + 4*NW4)
#define NCONV4 (NCONV/4)
#define NTAB (S_*64)

__global__ __launch_bounds__(256) void prologue_kernel(
    const float* __restrict__ X,
    const float* __restrict__ Wq, const float* __restrict__ Wk,
    const float* __restrict__ Wv, const float* __restrict__ Wo)
{
    int idx = blockIdx.x * 256 + threadIdx.x;
    if (idx < NCONV4) {
        int e = idx << 2;   // quad base
        const float* src;
        __half* dst;
        int off;
        if (e < NX4) {
            src = X; dst = g_Xh; off = e;
        } else {
            int t = e - NX4;
            int slot = t >> 20;
            off = t & (NW4 - 1);
            src = (slot == 0) ? Wq : (slot == 1) ? Wk : (slot == 2) ? Wv : Wo;
            dst = g_Wh + (size_t)slot * E_ * E_;
        }
        float4 v0 = ((const float4*)src)[off];
        float4 v1 = ((const float4*)src)[off + 1];
        float4 v2 = ((const float4*)src)[off + 2];
        float4 v3 = ((const float4*)src)[off + 3];
        uint4 h0, h1;
        h0.x = pack_f16(v0.x, v0.y); h0.y = pack_f16(v0.z, v0.w);
        h0.z = pack_f16(v1.x, v1.y); h0.w = pack_f16(v1.z, v1.w);
        h1.x = pack_f16(v2.x, v2.y); h1.y = pack_f16(v2.z, v2.w);
        h1.z = pack_f16(v3.x, v3.y); h1.w = pack_f16(v3.z, v3.w);
        ((uint4*)dst)[(off >> 1) + 0] = h0;
        ((uint4*)dst)[(off >> 1) + 1] = h1;
    } else {
        int t = idx - NCONV4;
        if (t < NTAB) {
            int p = t >> 6;
            int i = t & 63;
            float inv = powf(10000.0f, -(float)(2 * i) / 128.0f);
            float sn, cs;
            sincosf((float)p * inv, &sn, &cs);
            g_cos[t] = cs;
            g_sin[t] = sn;
        }
    }
}

// ---------------------------------------------------------------------------
// fp16 single-term GEMM (round-13 proven config): C[m,n] = sum_k A[m,k]*W[n,k]
// MODE 0: qkv (A = Xh), fused RoPE epilogue (Q pre-scaled).
// MODE 1: oproj (A = g_Ah), writes fp32 out.
// Block tile 128x128, 8 warps (warp tile 32x64), K-chunk 64, 2-stage,
// 2 CTAs/SM. Non-persistent.
// ---------------------------------------------------------------------------
#define KCH 64
#define NKC (E_/KCH)          // 32
#define ROWB 144              // 64 fp16 = 128B + 16B pad
#define TILE_B (128*ROWB)     // 18432
#define STG_B  (2*TILE_B)     // 36864: Ah, Bh
#define GEMM_SMEM 73728
#define CS_STRIDE 132

template<int MODE>
__global__ __launch_bounds__(256, 2) void gemm_mma(
    float* __restrict__ Oout, const int* __restrict__ posids)
{
    extern __shared__ char gsm[];
    const uint32_t sb = smem_to_u32(gsm);

    const int tid  = threadIdx.x;
    const int lane = tid & 31;
    const int wid  = tid >> 5;
    const int warpM = wid & 3;
    const int warpN = wid >> 2;
    const int m0 = blockIdx.y * 128;
    const int n0 = blockIdx.x * 128;
    const int z  = (MODE == 0) ? blockIdx.z : 3;

    const __half* Ahg = (MODE == 0) ? g_Xh : g_Ah;
    const __half* Bhg = g_Wh + (size_t)z * E_ * E_;

    const int lrow = tid >> 3;          // 0..31 (row base, +32 per it)
    const int lp   = tid & 7;           // 16B chunk within 128B row

    float c[2][8][4];
#pragma unroll
    for (int i = 0; i < 2; i++)
#pragma unroll
        for (int j = 0; j < 8; j++)
#pragma unroll
            for (int q = 0; q < 4; q++) c[i][j][q] = 0.f;

    const uint32_t aRow = (uint32_t)(warpM * 32 + (lane & 15)) * ROWB + (uint32_t)(lane >> 4) * 16;
    const uint32_t bRow = (uint32_t)(warpN * 64 + (lane & 7) + ((lane >> 4) << 3)) * ROWB
                        + (uint32_t)((lane >> 3) & 1) * 16;

    auto load_stage = [&](int buf, int kc) {
        const uint32_t stg = sb + buf * STG_B;
#pragma unroll
        for (int it = 0; it < 4; it++) {
            int row = lrow + it * 32;
            const size_t gA = (size_t)(m0 + row) * E_ + kc * KCH + lp * 8;
            const size_t gB = (size_t)(n0 + row) * E_ + kc * KCH + lp * 8;
            const uint32_t so = (uint32_t)(row * ROWB + lp * 16);
            CP_ASYNC16(stg + 0 * TILE_B + so, Ahg + gA);
            CP_ASYNC16(stg + 1 * TILE_B + so, Bhg + gB);
        }
        CP_ASYNC_COMMIT();
    };

    load_stage(0, 0);

    for (int kc = 0; kc < NKC; kc++) {
        const int buf = kc & 1;
        CP_ASYNC_WAIT0();
        __syncthreads();
        if (kc + 1 < NKC) load_stage(buf ^ 1, kc + 1);

        const uint32_t stg = sb + buf * STG_B;
#pragma unroll
        for (int ks = 0; ks < 4; ks++) {
            uint32_t ah[2][4], bh[4][4];
#pragma unroll
            for (int mi = 0; mi < 2; mi++) {
                uint32_t aoff = stg + aRow + (uint32_t)mi * 16 * ROWB + (uint32_t)ks * 32;
                ldsm_x4(ah[mi], aoff + 0 * TILE_B);
            }
#pragma unroll
            for (int g = 0; g < 4; g++) {
                uint32_t boff = stg + bRow + (uint32_t)g * 16 * ROWB + (uint32_t)ks * 32;
                ldsm_x4(bh[g], boff + 1 * TILE_B);
            }
#pragma unroll
            for (int mi = 0; mi < 2; mi++) {
#pragma unroll
                for (int g = 0; g < 4; g++) {
#pragma unroll
                    for (int hh = 0; hh < 2; hh++) {
                        mma16816(c[mi][2 * g + hh], ah[mi],
                                 bh[g][2 * hh], bh[g][2 * hh + 1]);
                    }
                }
            }
        }
        __syncthreads();
    }

    const int rr = lane >> 2;
    const int ct = 2 * (lane & 3);

    if (MODE == 1) {
#pragma unroll
        for (int mi = 0; mi < 2; mi++) {
#pragma unroll
            for (int ni = 0; ni < 8; ni++) {
                int row = m0 + warpM * 32 + mi * 16 + rr;
                int col = n0 + warpN * 64 + ni * 8 + ct;
                *(float2*)&Oout[(size_t)row * E_ + col] =
                    make_float2(c[mi][ni][0], c[mi][ni][1]);
                *(float2*)&Oout[(size_t)(row + 8) * E_ + col] =
                    make_float2(c[mi][ni][2], c[mi][ni][3]);
            }
        }
        return;
    }

    // ---- MODE 0 fused epilogue: stage C in smem, RoPE pair exchange ----
    float* Cs = (float*)gsm;
#pragma unroll
    for (int mi = 0; mi < 2; mi++) {
#pragma unroll
        for (int ni = 0; ni < 8; ni++) {
            int r = warpM * 32 + mi * 16 + rr;
            int ccol = warpN * 64 + ni * 8 + ct;
            *(float2*)&Cs[r * CS_STRIDE + ccol] =
                make_float2(c[mi][ni][0], c[mi][ni][1]);
            *(float2*)&Cs[(r + 8) * CS_STRIDE + ccol] =
                make_float2(c[mi][ni][2], c[mi][ni][3]);
        }
    }
    __syncthreads();

    const int headi = n0 >> 7;
    __half* Out = (z == 0) ? g_Qh : (z == 1) ? g_Kh : g_Vh;
    const float qsc = (z == 0) ? ASCALE : 1.0f;   // fold 1/sqrt(D) into Q

#pragma unroll
    for (int e = 0; e < 16; e++) {
        int idx = e * 256 + tid;
        int row = idx >> 5;
        int i2  = (idx & 31) << 1;
        int m = m0 + row;
        int bb = m >> 11, ss = m & (S_ - 1);
        size_t gbase = (((size_t)(bb * H_ + headi)) * S_ + ss) * D_;
        float2 xlo = *(float2*)&Cs[row * CS_STRIDE + i2];
        float2 xhi = *(float2*)&Cs[row * CS_STRIDE + i2 + 64];
        float o1x, o1y, o2x, o2y;
        if (z < 2) {
            int p = posids[bb * S_ + ss];
            float2 cs2 = *(float2*)&g_cos[p * 64 + i2];
            float2 sn2 = *(float2*)&g_sin[p * 64 + i2];
            o1x = (xlo.x * cs2.x - xhi.x * sn2.x) * qsc;
            o1y = (xlo.y * cs2.y - xhi.y * sn2.y) * qsc;
            o2x = (xhi.x * cs2.x + xlo.x * sn2.x) * qsc;
            o2y = (xhi.y * cs2.y + xlo.y * sn2.y) * qsc;
        } else {
            o1x = xlo.x; o1y = xlo.y; o2x = xhi.x; o2y = xhi.y;
        }
        *(uint32_t*)&Out[gbase + i2]      = pack_f16(o1x, o1y);
        *(uint32_t*)&Out[gbase + 64 + i2] = pack_f16(o2x, o2y);
    }
}

// ---------------------------------------------------------------------------
// Causal flash attention, fp16 single-term (round-13 proven config).
// Scores arrive pre-scaled (Q holds 1/sqrt(D)); exp2-based softmax.
// block = (qt, h, b); 8 warps (256 threads). BQ=128, BK=64, D=128.
// qt reversed so longest CTAs launch first. 2 CTAs/SM (smem 104448).
// ---------------------------------------------------------------------------
#define AROW 272                 // 128 fp16 = 256B + 16B pad
#define QTILE_B (128*AROW)       // 34816
#define KVTILE  (64*AROW)        // 17408
#define AQ_H 0
#define KV_BASE QTILE_B          // 34816
#define KVSTG (2*KVTILE)         // KH, VH = 34816
#define KV_KH 0
#define KV_VH KVTILE
#define ATTN_SMEM (KV_BASE + 2*KVSTG)  // 104448 -> 2 CTAs/SM

__global__ __launch_bounds__(256, 2) void attn_mma()
{
    const int qt = (int)(gridDim.x - 1 - blockIdx.x);   // long CTAs first
    const int h  = blockIdx.y;
    const int b  = blockIdx.z;

    extern __shared__ char asm_[];
    const uint32_t sb = smem_to_u32(asm_);

    const int tid  = threadIdx.x;
    const int lane = tid & 31;
    const int warp = tid >> 5;

    const size_t headoff = (((size_t)(b * H_ + h)) * S_) * D_;
    const __half* Qh = g_Qh + headoff;
    const __half* Kh = g_Kh + headoff;
    const __half* Vh = g_Vh + headoff;

    // Q tile: 128 x 128 fp16
#pragma unroll
    for (int it = 0; it < 8; it++) {
        int lin = it * 256 + tid;
        int row = lin >> 4;
        int ch  = lin & 15;
        const size_t src = (size_t)(qt * 128 + row) * D_ + ch * 8;
        uint32_t dst = (uint32_t)(row * AROW + ch * 16);
        CP_ASYNC16(sb + AQ_H + dst, Qh + src);
    }
    CP_ASYNC_COMMIT();

    auto load_kv = [&](int bufi, int kt) {
        const uint32_t stg = sb + KV_BASE + bufi * KVSTG;
#pragma unroll
        for (int it = 0; it < 4; it++) {
            int lin = it * 256 + tid;
            int row = lin >> 4;
            int ch  = lin & 15;
            const size_t src = (size_t)(kt * 64 + row) * D_ + ch * 8;
            uint32_t dst = (uint32_t)(row * AROW + ch * 16);
            CP_ASYNC16(stg + KV_KH + dst, Kh + src);
            CP_ASYNC16(stg + KV_VH + dst, Vh + src);
        }
        CP_ASYNC_COMMIT();
    };

    load_kv(0, 0);
    CP_ASYNC_WAIT0();
    __syncthreads();

    const uint32_t aRow = (uint32_t)(warp * 16 + (lane & 15)) * AROW
                        + (uint32_t)(lane >> 4) * 16;
    const uint32_t bRow = (uint32_t)((lane & 7) + ((lane >> 4) << 3)) * AROW
                        + (uint32_t)((lane >> 3) & 1) * 16;
    const uint32_t vRow = (uint32_t)(lane & 15) * AROW
                        + (uint32_t)(lane >> 4) * 16;

    float m0r = -INFINITY, m1r = -INFINITY, l0r = 0.f, l1r = 0.f;
    float co[16][4];
#pragma unroll
    for (int j = 0; j < 16; j++)
#pragma unroll
        for (int q = 0; q < 4; q++) co[j][q] = 0.f;

    const int qrow0 = qt * 128 + warp * 16 + (lane >> 2);
    const int qrow1 = qrow0 + 8;
    const int nkt = 2 * qt + 2;

    for (int kt = 0; kt < nkt; kt++) {
        const int bufi = kt & 1;
        if (kt + 1 < nkt) load_kv(bufi ^ 1, kt + 1);
        const uint32_t kvs = sb + KV_BASE + bufi * KVSTG;

        // --- S = Q K^T (single term), scores already scaled ---
        float s[8][4];
#pragma unroll
        for (int j = 0; j < 8; j++)
#pragma unroll
            for (int q = 0; q < 4; q++) s[j][q] = 0.f;

#pragma unroll
        for (int kd = 0; kd < 8; kd++) {
            uint32_t qh_[4];
            ldsm_x4(qh_, sb + AQ_H + aRow + kd * 32);
#pragma unroll
            for (int g = 0; g < 4; g++) {
                uint32_t kbh[4];
                uint32_t boff = bRow + (uint32_t)g * 16 * AROW + (uint32_t)kd * 32;
                ldsm_x4(kbh, kvs + KV_KH + boff);
#pragma unroll
                for (int hh = 0; hh < 2; hh++) {
                    mma16816(s[2 * g + hh], qh_, kbh[2 * hh], kbh[2 * hh + 1]);
                }
            }
        }

        // --- causal mask ---
        if (kt >= 2 * qt) {
            const int kbase = kt * 64 + 2 * (lane & 3);
#pragma unroll
            for (int j = 0; j < 8; j++) {
                int k0 = kbase + 8 * j;
                if (k0 > qrow0)     s[j][0] = -INFINITY;
                if (k0 + 1 > qrow0) s[j][1] = -INFINITY;
                if (k0 > qrow1)     s[j][2] = -INFINITY;
                if (k0 + 1 > qrow1) s[j][3] = -INFINITY;
            }
        }

        // --- online softmax (exp2 with log2e fold) ---
        float mx0 = s[0][0], mx1 = s[0][2];
#pragma unroll
        for (int j = 0; j < 8; j++) {
            mx0 = fmaxf(mx0, fmaxf(s[j][0], s[j][1]));
            mx1 = fmaxf(mx1, fmaxf(s[j][2], s[j][3]));
        }
        mx0 = fmaxf(mx0, __shfl_xor_sync(0xffffffffu, mx0, 1));
        mx0 = fmaxf(mx0, __shfl_xor_sync(0xffffffffu, mx0, 2));
        mx1 = fmaxf(mx1, __shfl_xor_sync(0xffffffffu, mx1, 1));
        mx1 = fmaxf(mx1, __shfl_xor_sync(0xffffffffu, mx1, 2));

        float mn0 = fmaxf(m0r, mx0), mn1 = fmaxf(m1r, mx1);
        float corr0 = exp2f((m0r - mn0) * LOG2E);
        float corr1 = exp2f((m1r - mn1) * LOG2E);
        m0r = mn0; m1r = mn1;
        const float b0 = mn0 * LOG2E;
        const float b1 = mn1 * LOG2E;

        float rs0 = 0.f, rs1 = 0.f;
#pragma unroll
        for (int j = 0; j < 8; j++) {
            s[j][0] = exp2f(fmaf(s[j][0], LOG2E, -b0));
            s[j][1] = exp2f(fmaf(s[j][1], LOG2E, -b0));
            s[j][2] = exp2f(fmaf(s[j][2], LOG2E, -b1));
            s[j][3] = exp2f(fmaf(s[j][3], LOG2E, -b1));
            rs0 += s[j][0] + s[j][1];
            rs1 += s[j][2] + s[j][3];
        }
        rs0 += __shfl_xor_sync(0xffffffffu, rs0, 1);
        rs0 += __shfl_xor_sync(0xffffffffu, rs0, 2);
        rs1 += __shfl_xor_sync(0xffffffffu, rs1, 1);
        rs1 += __shfl_xor_sync(0xffffffffu, rs1, 2);
        l0r = l0r * corr0 + rs0;
        l1r = l1r * corr1 + rs1;

#pragma unroll
        for (int j = 0; j < 16; j++) {
            co[j][0] *= corr0; co[j][1] *= corr0;
            co[j][2] *= corr1; co[j][3] *= corr1;
        }

        // --- O += P V (single term) ---
#pragma unroll
        for (int ks = 0; ks < 4; ks++) {
            float* cA = s[2 * ks];
            float* cB = s[2 * ks + 1];
            uint32_t ph[4];
            ph[0] = pack_f16(cA[0], cA[1]);
            ph[1] = pack_f16(cA[2], cA[3]);
            ph[2] = pack_f16(cB[0], cB[1]);
            ph[3] = pack_f16(cB[2], cB[3]);
#pragma unroll
            for (int dd = 0; dd < 8; dd++) {
                uint32_t vh_[4];
                uint32_t voff = vRow + (uint32_t)ks * 16 * AROW + (uint32_t)dd * 32;
                ldsm_x4_trans(vh_, kvs + KV_VH + voff);
                mma16816(co[2 * dd],     ph, vh_[0], vh_[1]);
                mma16816(co[2 * dd + 1], ph, vh_[2], vh_[3]);
            }
        }

        if (kt + 1 < nkt) CP_ASYNC_WAIT0();
        __syncthreads();
    }

    // --- epilogue: normalize, write A (single fp16) ---
    const float invl0 = 1.f / l0r;
    const float invl1 = 1.f / l1r;
    const int t2 = 2 * (lane & 3);
    const size_t rowA0 = ((size_t)(b * S_ + qrow0)) * E_ + h * D_;
    const size_t rowA1 = ((size_t)(b * S_ + qrow1)) * E_ + h * D_;
#pragma unroll
    for (int j = 0; j < 16; j++) {
        int col = 8 * j + t2;
        float a0 = co[j][0] * invl0, a1 = co[j][1] * invl0;
        float a2 = co[j][2] * invl1, a3 = co[j][3] * invl1;
        *(uint32_t*)&g_Ah[rowA0 + col] = pack_f16(a0, a1);
        *(uint32_t*)&g_Ah[rowA1 + col] = pack_f16(a2, a3);
    }
}

// ---------------------------------------------------------------------------
extern "C" void kernel_launch(void* const* d_in, const int* in_sizes, int n_in,
                              void* d_out, int out_size)
{
    const float* hidden = (const float*)d_in[0];
    const int*   posids = (const int*)d_in[2];
    const float* Wq     = (const float*)d_in[3];
    const float* Wk     = (const float*)d_in[4];
    const float* Wv     = (const float*)d_in[5];
    const float* Wo     = (const float*)d_in[6];
    float*       out    = (float*)d_out;

    cudaFuncSetAttribute(gemm_mma<0>,
                         cudaFuncAttributeMaxDynamicSharedMemorySize, GEMM_SMEM);
    cudaFuncSetAttribute(gemm_mma<1>,
                         cudaFuncAttributeMaxDynamicSharedMemorySize, GEMM_SMEM);
    cudaFuncSetAttribute(attn_mma,
                         cudaFuncAttributeMaxDynamicSharedMemorySize, ATTN_SMEM);

    // 1) merged prologue: fp16 converts (64B/thread) + RoPE table
    {
        int total = NCONV4 + NTAB;
        prologue_kernel<<<(total + 255) / 256, 256>>>(hidden, Wq, Wk, Wv, Wo);
    }
    // 2) QKV projections (round-13 GEMM) + fused RoPE epilogue
    {
        dim3 grid(E_ / 128, M_ / 128, 3);
        gemm_mma<0><<<grid, 256, GEMM_SMEM>>>(nullptr, posids);
    }
    // 3) causal flash attention -> g_Ah
    {
        dim3 grid(S_ / 128, H_, B_);
        attn_mma<<<grid, 256, ATTN_SMEM>>>();
    }
    // 4) output projection -> d_out
    {
        dim3 grid(E_ / 128, M_ / 128);
        gemm_mma<1><<<grid, 256, GEMM_SMEM>>>(out, nullptr);
    }
}

// round 16
// speedup vs baseline: 1.0788x; 1.0046x over previous
#include <cuda_runtime.h>
#include <cuda_fp16.h>
#include <math.h>
#include <float.h>
#include <stdint.h>

// Problem dims
#define B_ 2
#define S_ 2048
#define H_ 16
#define D_ 128
#define E_ 2048
#define M_ (B_*S_)   // 4096 tokens

// fp16 operands (all single-rn)
__device__ __half g_Xh[M_*E_];       // X single fp16
__device__ __half g_Wh[4*E_*E_];     // (q,k,v,o) single fp16
__device__ __half g_Ah[M_*E_];       // attention output single fp16 [B,S,E]
// post-RoPE QKV in [B,H,S,D], single fp16 (Q pre-scaled by 1/sqrt(D))
__device__ __half g_Qh[B_*H_*S_*D_];
__device__ __half g_Kh[B_*H_*S_*D_];
__device__ __half g_Vh[B_*H_*S_*D_];
// RoPE tables [pos][i] for i in 0..63
__device__ float g_cos[S_*64];
__device__ float g_sin[S_*64];

#define ASCALE 0.088388347648318447f   // 1/sqrt(128), folded into Q
#define LOG2E  1.4426950408889634f

__device__ __forceinline__ uint32_t smem_to_u32(const void* smem_ptr) {
    uint32_t addr;
    asm("{ .reg .u64 tmp; cvta.to.shared.u64 tmp, %1; cvt.u32.u64 %0, tmp; }"
        : "=r"(addr) : "l"(smem_ptr));
    return addr;
}

#define CP_ASYNC16(dst, src) \
    asm volatile("cp.async.cg.shared.global [%0], [%1], 16;" \
        :: "r"(dst), "l"(src) : "memory")
#define CP_ASYNC_COMMIT() asm volatile("cp.async.commit_group;" ::: "memory")
#define CP_ASYNC_WAIT0()  asm volatile("cp.async.wait_group 0;" ::: "memory")

__device__ __forceinline__ void ldsm_x4(uint32_t* r, uint32_t addr) {
    asm volatile("ldmatrix.sync.aligned.m8n8.x4.shared.b16 {%0,%1,%2,%3}, [%4];"
        : "=r"(r[0]), "=r"(r[1]), "=r"(r[2]), "=r"(r[3]) : "r"(addr));
}
__device__ __forceinline__ void ldsm_x4_trans(uint32_t* r, uint32_t addr) {
    asm volatile("ldmatrix.sync.aligned.m8n8.x4.trans.shared.b16 {%0,%1,%2,%3}, [%4];"
        : "=r"(r[0]), "=r"(r[1]), "=r"(r[2]), "=r"(r[3]) : "r"(addr));
}

__device__ __forceinline__ void mma16816(float* c, const uint32_t* a,
                                          uint32_t b0, uint32_t b1) {
    asm volatile(
        "mma.sync.aligned.m16n8k16.row.col.f32.f16.f16.f32 "
        "{%0,%1,%2,%3}, {%4,%5,%6,%7}, {%8,%9}, {%0,%1,%2,%3};"
        : "+f"(c[0]), "+f"(c[1]), "+f"(c[2]), "+f"(c[3])
        : "r"(a[0]), "r"(a[1]), "r"(a[2]), "r"(a[3]), "r"(b0), "r"(b1));
}

__device__ __forceinline__ uint32_t pack_f16(float a, float b) {
    __half2 p = __halves2half2(__float2half_rn(a), __float2half_rn(b));
    return *(uint32_t*)&p;
}

// ---------------------------------------------------------------------------
// Merged prologue: X + 4 weights -> fp16 rn (64B per thread), + RoPE table.
// ---------------------------------------------------------------------------
#define NX4 (M_*E_/4)    // 2^21
#define NW4 (E_*E_/4)    // 2^20
#define NCONV (NX4 + 4*NW4)
#define NCONV4 (NCONV/4)
#define NTAB (S_*64)

__global__ __launch_bounds__(256) void prologue_kernel(
    const float* __restrict__ X,
    const float* __restrict__ Wq, const float* __restrict__ Wk,
    const float* __restrict__ Wv, const float* __restrict__ Wo)
{
    int idx = blockIdx.x * 256 + threadIdx.x;
    if (idx < NCONV4) {
        int e = idx << 2;   // quad base
        const float* src;
        __half* dst;
        int off;
        if (e < NX4) {
            src = X; dst = g_Xh; off = e;
        } else {
            int t = e - NX4;
            int slot = t >> 20;
            off = t & (NW4 - 1);
            src = (slot == 0) ? Wq : (slot == 1) ? Wk : (slot == 2) ? Wv : Wo;
            dst = g_Wh + (size_t)slot * E_ * E_;
        }
        float4 v0 = ((const float4*)src)[off];
        float4 v1 = ((const float4*)src)[off + 1];
        float4 v2 = ((const float4*)src)[off + 2];
        float4 v3 = ((const float4*)src)[off + 3];
        uint4 h0, h1;
        h0.x = pack_f16(v0.x, v0.y); h0.y = pack_f16(v0.z, v0.w);
        h0.z = pack_f16(v1.x, v1.y); h0.w = pack_f16(v1.z, v1.w);
        h1.x = pack_f16(v2.x, v2.y); h1.y = pack_f16(v2.z, v2.w);
        h1.z = pack_f16(v3.x, v3.y); h1.w = pack_f16(v3.z, v3.w);
        ((uint4*)dst)[(off >> 1) + 0] = h0;
        ((uint4*)dst)[(off >> 1) + 1] = h1;
    } else {
        int t = idx - NCONV4;
        if (t < NTAB) {
            int p = t >> 6;
            int i = t & 63;
            float inv = powf(10000.0f, -(float)(2 * i) / 128.0f);
            float sn, cs;
            sincosf((float)p * inv, &sn, &cs);
            g_cos[t] = cs;
            g_sin[t] = sn;
        }
    }
}

// ---------------------------------------------------------------------------
// fp16 single-term GEMM (round-13/15 proven config).
// MODE 0: qkv (A = Xh), fused RoPE epilogue (Q pre-scaled).
// MODE 1: oproj (A = g_Ah), writes fp32 out.
// Block tile 128x128, 8 warps (warp tile 32x64), K-chunk 64, 2-stage,
// 2 CTAs/SM. Non-persistent.
// ---------------------------------------------------------------------------
#define KCH 64
#define NKC (E_/KCH)          // 32
#define ROWB 144              // 64 fp16 = 128B + 16B pad
#define TILE_B (128*ROWB)     // 18432
#define STG_B  (2*TILE_B)     // 36864: Ah, Bh
#define GEMM_SMEM 73728
#define CS_STRIDE 132

template<int MODE>
__global__ __launch_bounds__(256, 2) void gemm_mma(
    float* __restrict__ Oout, const int* __restrict__ posids)
{
    extern __shared__ char gsm[];
    const uint32_t sb = smem_to_u32(gsm);

    const int tid  = threadIdx.x;
    const int lane = tid & 31;
    const int wid  = tid >> 5;
    const int warpM = wid & 3;
    const int warpN = wid >> 2;
    const int m0 = blockIdx.y * 128;
    const int n0 = blockIdx.x * 128;
    const int z  = (MODE == 0) ? blockIdx.z : 3;

    const __half* Ahg = (MODE == 0) ? g_Xh : g_Ah;
    const __half* Bhg = g_Wh + (size_t)z * E_ * E_;

    const int lrow = tid >> 3;          // 0..31 (row base, +32 per it)
    const int lp   = tid & 7;           // 16B chunk within 128B row

    float c[2][8][4];
#pragma unroll
    for (int i = 0; i < 2; i++)
#pragma unroll
        for (int j = 0; j < 8; j++)
#pragma unroll
            for (int q = 0; q < 4; q++) c[i][j][q] = 0.f;

    const uint32_t aRow = (uint32_t)(warpM * 32 + (lane & 15)) * ROWB + (uint32_t)(lane >> 4) * 16;
    const uint32_t bRow = (uint32_t)(warpN * 64 + (lane & 7) + ((lane >> 4) << 3)) * ROWB
                        + (uint32_t)((lane >> 3) & 1) * 16;

    auto load_stage = [&](int buf, int kc) {
        const uint32_t stg = sb + buf * STG_B;
#pragma unroll
        for (int it = 0; it < 4; it++) {
            int row = lrow + it * 32;
            const size_t gA = (size_t)(m0 + row) * E_ + kc * KCH + lp * 8;
            const size_t gB = (size_t)(n0 + row) * E_ + kc * KCH + lp * 8;
            const uint32_t so = (uint32_t)(row * ROWB + lp * 16);
            CP_ASYNC16(stg + 0 * TILE_B + so, Ahg + gA);
            CP_ASYNC16(stg + 1 * TILE_B + so, Bhg + gB);
        }
        CP_ASYNC_COMMIT();
    };

    load_stage(0, 0);

    for (int kc = 0; kc < NKC; kc++) {
        const int buf = kc & 1;
        CP_ASYNC_WAIT0();
        __syncthreads();
        if (kc + 1 < NKC) load_stage(buf ^ 1, kc + 1);

        const uint32_t stg = sb + buf * STG_B;
#pragma unroll
        for (int ks = 0; ks < 4; ks++) {
            uint32_t ah[2][4], bh[4][4];
#pragma unroll
            for (int mi = 0; mi < 2; mi++) {
                uint32_t aoff = stg + aRow + (uint32_t)mi * 16 * ROWB + (uint32_t)ks * 32;
                ldsm_x4(ah[mi], aoff + 0 * TILE_B);
            }
#pragma unroll
            for (int g = 0; g < 4; g++) {
                uint32_t boff = stg + bRow + (uint32_t)g * 16 * ROWB + (uint32_t)ks * 32;
                ldsm_x4(bh[g], boff + 1 * TILE_B);
            }
#pragma unroll
            for (int mi = 0; mi < 2; mi++) {
#pragma unroll
                for (int g = 0; g < 4; g++) {
#pragma unroll
                    for (int hh = 0; hh < 2; hh++) {
                        mma16816(c[mi][2 * g + hh], ah[mi],
                                 bh[g][2 * hh], bh[g][2 * hh + 1]);
                    }
                }
            }
        }
        __syncthreads();
    }

    const int rr = lane >> 2;
    const int ct = 2 * (lane & 3);

    if (MODE == 1) {
#pragma unroll
        for (int mi = 0; mi < 2; mi++) {
#pragma unroll
            for (int ni = 0; ni < 8; ni++) {
                int row = m0 + warpM * 32 + mi * 16 + rr;
                int col = n0 + warpN * 64 + ni * 8 + ct;
                *(float2*)&Oout[(size_t)row * E_ + col] =
                    make_float2(c[mi][ni][0], c[mi][ni][1]);
                *(float2*)&Oout[(size_t)(row + 8) * E_ + col] =
                    make_float2(c[mi][ni][2], c[mi][ni][3]);
            }
        }
        return;
    }

    // ---- MODE 0 fused epilogue: stage C in smem, RoPE pair exchange ----
    float* Cs = (float*)gsm;
#pragma unroll
    for (int mi = 0; mi < 2; mi++) {
#pragma unroll
        for (int ni = 0; ni < 8; ni++) {
            int r = warpM * 32 + mi * 16 + rr;
            int ccol = warpN * 64 + ni * 8 + ct;
            *(float2*)&Cs[r * CS_STRIDE + ccol] =
                make_float2(c[mi][ni][0], c[mi][ni][1]);
            *(float2*)&Cs[(r + 8) * CS_STRIDE + ccol] =
                make_float2(c[mi][ni][2], c[mi][ni][3]);
        }
    }
    __syncthreads();

    const int headi = n0 >> 7;
    __half* Out = (z == 0) ? g_Qh : (z == 1) ? g_Kh : g_Vh;
    const float qsc = (z == 0) ? ASCALE : 1.0f;   // fold 1/sqrt(D) into Q

#pragma unroll
    for (int e = 0; e < 16; e++) {
        int idx = e * 256 + tid;
        int row = idx >> 5;
        int i2  = (idx & 31) << 1;
        int m = m0 + row;
        int bb = m >> 11, ss = m & (S_ - 1);
        size_t gbase = (((size_t)(bb * H_ + headi)) * S_ + ss) * D_;
        float2 xlo = *(float2*)&Cs[row * CS_STRIDE + i2];
        float2 xhi = *(float2*)&Cs[row * CS_STRIDE + i2 + 64];
        float o1x, o1y, o2x, o2y;
        if (z < 2) {
            int p = posids[bb * S_ + ss];
            float2 cs2 = *(float2*)&g_cos[p * 64 + i2];
            float2 sn2 = *(float2*)&g_sin[p * 64 + i2];
            o1x = (xlo.x * cs2.x - xhi.x * sn2.x) * qsc;
            o1y = (xlo.y * cs2.y - xhi.y * sn2.y) * qsc;
            o2x = (xhi.x * cs2.x + xlo.x * sn2.x) * qsc;
            o2y = (xhi.y * cs2.y + xlo.y * sn2.y) * qsc;
        } else {
            o1x = xlo.x; o1y = xlo.y; o2x = xhi.x; o2y = xhi.y;
        }
        *(uint32_t*)&Out[gbase + i2]      = pack_f16(o1x, o1y);
        *(uint32_t*)&Out[gbase + 64 + i2] = pack_f16(o2x, o2y);
    }
}

// ---------------------------------------------------------------------------
// Causal flash attention, fp16 single-term. Deferred-l softmax: the row-sum
// reduction across the quad happens ONCE in the epilogue, not per kt (the max
// reduction stays per-kt since P must be consistent across the quad).
// block = (qt, h, b); 8 warps (256 threads). BQ=128, BK=64, D=128.
// qt reversed so longest CTAs launch first. 2 CTAs/SM (smem 104448).
// ---------------------------------------------------------------------------
#define AROW 272                 // 128 fp16 = 256B + 16B pad
#define QTILE_B (128*AROW)       // 34816
#define KVTILE  (64*AROW)        // 17408
#define AQ_H 0
#define KV_BASE QTILE_B          // 34816
#define KVSTG (2*KVTILE)         // KH, VH = 34816
#define KV_KH 0
#define KV_VH KVTILE
#define ATTN_SMEM (KV_BASE + 2*KVSTG)  // 104448 -> 2 CTAs/SM

__global__ __launch_bounds__(256, 2) void attn_mma()
{
    const int qt = (int)(gridDim.x - 1 - blockIdx.x);   // long CTAs first
    const int h  = blockIdx.y;
    const int b  = blockIdx.z;

    extern __shared__ char asm_[];
    const uint32_t sb = smem_to_u32(asm_);

    const int tid  = threadIdx.x;
    const int lane = tid & 31;
    const int warp = tid >> 5;

    const size_t headoff = (((size_t)(b * H_ + h)) * S_) * D_;
    const __half* Qh = g_Qh + headoff;
    const __half* Kh = g_Kh + headoff;
    const __half* Vh = g_Vh + headoff;

    // Q tile: 128 x 128 fp16
#pragma unroll
    for (int it = 0; it < 8; it++) {
        int lin = it * 256 + tid;
        int row = lin >> 4;
        int ch  = lin & 15;
        const size_t src = (size_t)(qt * 128 + row) * D_ + ch * 8;
        uint32_t dst = (uint32_t)(row * AROW + ch * 16);
        CP_ASYNC16(sb + AQ_H + dst, Qh + src);
    }
    CP_ASYNC_COMMIT();

    auto load_kv = [&](int bufi, int kt) {
        const uint32_t stg = sb + KV_BASE + bufi * KVSTG;
#pragma unroll
        for (int it = 0; it < 4; it++) {
            int lin = it * 256 + tid;
            int row = lin >> 4;
            int ch  = lin & 15;
            const size_t src = (size_t)(kt * 64 + row) * D_ + ch * 8;
            uint32_t dst = (uint32_t)(row * AROW + ch * 16);
            CP_ASYNC16(stg + KV_KH + dst, Kh + src);
            CP_ASYNC16(stg + KV_VH + dst, Vh + src);
        }
        CP_ASYNC_COMMIT();
    };

    load_kv(0, 0);
    CP_ASYNC_WAIT0();
    __syncthreads();

    const uint32_t aRow = (uint32_t)(warp * 16 + (lane & 15)) * AROW
                        + (uint32_t)(lane >> 4) * 16;
    const uint32_t bRow = (uint32_t)((lane & 7) + ((lane >> 4) << 3)) * AROW
                        + (uint32_t)((lane >> 3) & 1) * 16;
    const uint32_t vRow = (uint32_t)(lane & 15) * AROW
                        + (uint32_t)(lane >> 4) * 16;

    float m0r = -INFINITY, m1r = -INFINITY;
    float l0r = 0.f, l1r = 0.f;          // PER-THREAD partial sums (deferred)
    float co[16][4];
#pragma unroll
    for (int j = 0; j < 16; j++)
#pragma unroll
        for (int q = 0; q < 4; q++) co[j][q] = 0.f;

    const int qrow0 = qt * 128 + warp * 16 + (lane >> 2);
    const int qrow1 = qrow0 + 8;
    const int nkt = 2 * qt + 2;

    for (int kt = 0; kt < nkt; kt++) {
        const int bufi = kt & 1;
        if (kt + 1 < nkt) load_kv(bufi ^ 1, kt + 1);
        const uint32_t kvs = sb + KV_BASE + bufi * KVSTG;

        // --- S = Q K^T (single term), scores already scaled ---
        float s[8][4];
#pragma unroll
        for (int j = 0; j < 8; j++)
#pragma unroll
            for (int q = 0; q < 4; q++) s[j][q] = 0.f;

#pragma unroll
        for (int kd = 0; kd < 8; kd++) {
            uint32_t qh_[4];
            ldsm_x4(qh_, sb + AQ_H + aRow + kd * 32);
#pragma unroll
            for (int g = 0; g < 4; g++) {
                uint32_t kbh[4];
                uint32_t boff = bRow + (uint32_t)g * 16 * AROW + (uint32_t)kd * 32;
                ldsm_x4(kbh, kvs + KV_KH + boff);
#pragma unroll
                for (int hh = 0; hh < 2; hh++) {
                    mma16816(s[2 * g + hh], qh_, kbh[2 * hh], kbh[2 * hh + 1]);
                }
            }
        }

        // --- causal mask ---
        if (kt >= 2 * qt) {
            const int kbase = kt * 64 + 2 * (lane & 3);
#pragma unroll
            for (int j = 0; j < 8; j++) {
                int k0 = kbase + 8 * j;
                if (k0 > qrow0)     s[j][0] = -INFINITY;
                if (k0 + 1 > qrow0) s[j][1] = -INFINITY;
                if (k0 > qrow1)     s[j][2] = -INFINITY;
                if (k0 + 1 > qrow1) s[j][3] = -INFINITY;
            }
        }

        // --- online softmax: max must be quad-consistent; sum is deferred ---
        float mx0 = s[0][0], mx1 = s[0][2];
#pragma unroll
        for (int j = 0; j < 8; j++) {
            mx0 = fmaxf(mx0, fmaxf(s[j][0], s[j][1]));
            mx1 = fmaxf(mx1, fmaxf(s[j][2], s[j][3]));
        }
        mx0 = fmaxf(mx0, __shfl_xor_sync(0xffffffffu, mx0, 1));
        mx0 = fmaxf(mx0, __shfl_xor_sync(0xffffffffu, mx0, 2));
        mx1 = fmaxf(mx1, __shfl_xor_sync(0xffffffffu, mx1, 1));
        mx1 = fmaxf(mx1, __shfl_xor_sync(0xffffffffu, mx1, 2));

        float mn0 = fmaxf(m0r, mx0), mn1 = fmaxf(m1r, mx1);
        float corr0 = exp2f((m0r - mn0) * LOG2E);
        float corr1 = exp2f((m1r - mn1) * LOG2E);
        m0r = mn0; m1r = mn1;
        const float b0 = mn0 * LOG2E;
        const float b1 = mn1 * LOG2E;

        float rs0 = 0.f, rs1 = 0.f;    // this thread's 2x16 columns only
#pragma unroll
        for (int j = 0; j < 8; j++) {
            s[j][0] = exp2f(fmaf(s[j][0], LOG2E, -b0));
            s[j][1] = exp2f(fmaf(s[j][1], LOG2E, -b0));
            s[j][2] = exp2f(fmaf(s[j][2], LOG2E, -b1));
            s[j][3] = exp2f(fmaf(s[j][3], LOG2E, -b1));
            rs0 += s[j][0] + s[j][1];
            rs1 += s[j][2] + s[j][3];
        }
        // NO shfl here: l stays a per-thread partial, reduced in epilogue.
        l0r = l0r * corr0 + rs0;
        l1r = l1r * corr1 + rs1;

#pragma unroll
        for (int j = 0; j < 16; j++) {
            co[j][0] *= corr0; co[j][1] *= corr0;
            co[j][2] *= corr1; co[j][3] *= corr1;
        }

        // --- O += P V (single term) ---
#pragma unroll
        for (int ks = 0; ks < 4; ks++) {
            float* cA = s[2 * ks];
            float* cB = s[2 * ks + 1];
            uint32_t ph[4];
            ph[0] = pack_f16(cA[0], cA[1]);
            ph[1] = pack_f16(cA[2], cA[3]);
            ph[2] = pack_f16(cB[0], cB[1]);
            ph[3] = pack_f16(cB[2], cB[3]);
#pragma unroll
            for (int dd = 0; dd < 8; dd++) {
                uint32_t vh_[4];
                uint32_t voff = vRow + (uint32_t)ks * 16 * AROW + (uint32_t)dd * 32;
                ldsm_x4_trans(vh_, kvs + KV_VH + voff);
                mma16816(co[2 * dd],     ph, vh_[0], vh_[1]);
                mma16816(co[2 * dd + 1], ph, vh_[2], vh_[3]);
            }
        }

        if (kt + 1 < nkt) CP_ASYNC_WAIT0();
        __syncthreads();
    }

    // --- epilogue: reduce l across the quad ONCE, normalize, write A ---
    l0r += __shfl_xor_sync(0xffffffffu, l0r, 1);
    l0r += __shfl_xor_sync(0xffffffffu, l0r, 2);
    l1r += __shfl_xor_sync(0xffffffffu, l1r, 1);
    l1r += __shfl_xor_sync(0xffffffffu, l1r, 2);
    const float invl0 = 1.f / l0r;
    const float invl1 = 1.f / l1r;
    const int t2 = 2 * (lane & 3);
    const size_t rowA0 = ((size_t)(b * S_ + qrow0)) * E_ + h * D_;
    const size_t rowA1 = ((size_t)(b * S_ + qrow1)) * E_ + h * D_;
#pragma unroll
    for (int j = 0; j < 16; j++) {
        int col = 8 * j + t2;
        float a0 = co[j][0] * invl0, a1 = co[j][1] * invl0;
        float a2 = co[j][2] * invl1, a3 = co[j][3] * invl1;
        *(uint32_t*)&g_Ah[rowA0 + col] = pack_f16(a0, a1);
        *(uint32_t*)&g_Ah[rowA1 + col] = pack_f16(a2, a3);
    }
}

// ---------------------------------------------------------------------------
extern "C" void kernel_launch(void* const* d_in, const int* in_sizes, int n_in,
                              void* d_out, int out_size)
{
    const float* hidden = (const float*)d_in[0];
    const int*   posids = (const int*)d_in[2];
    const float* Wq     = (const float*)d_in[3];
    const float* Wk     = (const float*)d_in[4];
    const float* Wv     = (const float*)d_in[5];
    const float* Wo     = (const float*)d_in[6];
    float*       out    = (float*)d_out;

    cudaFuncSetAttribute(gemm_mma<0>,
                         cudaFuncAttributeMaxDynamicSharedMemorySize, GEMM_SMEM);
    cudaFuncSetAttribute(gemm_mma<1>,
                         cudaFuncAttributeMaxDynamicSharedMemorySize, GEMM_SMEM);
    cudaFuncSetAttribute(attn_mma,
                         cudaFuncAttributeMaxDynamicSharedMemorySize, ATTN_SMEM);

    // 1) merged prologue: fp16 converts (64B/thread) + RoPE table
    {
        int total = NCONV4 + NTAB;
        prologue_kernel<<<(total + 255) / 256, 256>>>(hidden, Wq, Wk, Wv, Wo);
    }
    // 2) QKV projections + fused RoPE epilogue
    {
        dim3 grid(E_ / 128, M_ / 128, 3);
        gemm_mma<0><<<grid, 256, GEMM_SMEM>>>(nullptr, posids);
    }
    // 3) causal flash attention (deferred-l softmax) -> g_Ah
    {
        dim3 grid(S_ / 128, H_, B_);
        attn_mma<<<grid, 256, ATTN_SMEM>>>();
    }
    // 4) output projection -> d_out
    {
        dim3 grid(E_ / 128, M_ / 128);
        gemm_mma<1><<<grid, 256, GEMM_SMEM>>>(out, nullptr);
    }
}

// round 17
// speedup vs baseline: 1.1565x; 1.0720x over previous
#include <cuda_runtime.h>
#include <cuda_fp16.h>
#include <math.h>
#include <float.h>
#include <stdint.h>

// Problem dims
#define B_ 2
#define S_ 2048
#define H_ 16
#define D_ 128
#define E_ 2048
#define M_ (B_*S_)   // 4096 tokens

// fp16 operands (all single-rn)
__device__ __half g_Xh[M_*E_];       // X single fp16
__device__ __half g_Wh[4*E_*E_];     // (q,k,v,o) single fp16
__device__ __half g_Ah[M_*E_];       // attention output single fp16 [B,S,E]
// post-RoPE QKV in [B,H,S,D], single fp16 (Q pre-scaled by 1/sqrt(D))
__device__ __half g_Qh[B_*H_*S_*D_];
__device__ __half g_Kh[B_*H_*S_*D_];
__device__ __half g_Vh[B_*H_*S_*D_];
// RoPE tables [pos][i] for i in 0..63
__device__ float g_cos[S_*64];
__device__ float g_sin[S_*64];
// work-stealing counter for persistent attention
__device__ unsigned int g_work;

#define ASCALE 0.088388347648318447f   // 1/sqrt(128), folded into Q
#define LOG2E  1.4426950408889634f
#define N_ITEMS 512                    // 16 qt-tiles x 16 heads x 2 batch

__device__ __forceinline__ uint32_t smem_to_u32(const void* smem_ptr) {
    uint32_t addr;
    asm("{ .reg .u64 tmp; cvta.to.shared.u64 tmp, %1; cvt.u32.u64 %0, tmp; }"
        : "=r"(addr) : "l"(smem_ptr));
    return addr;
}

#define CP_ASYNC16(dst, src) \
    asm volatile("cp.async.cg.shared.global [%0], [%1], 16;" \
        :: "r"(dst), "l"(src) : "memory")
#define CP_ASYNC_COMMIT() asm volatile("cp.async.commit_group;" ::: "memory")
#define CP_ASYNC_WAIT0()  asm volatile("cp.async.wait_group 0;" ::: "memory")

__device__ __forceinline__ void ldsm_x4(uint32_t* r, uint32_t addr) {
    asm volatile("ldmatrix.sync.aligned.m8n8.x4.shared.b16 {%0,%1,%2,%3}, [%4];"
        : "=r"(r[0]), "=r"(r[1]), "=r"(r[2]), "=r"(r[3]) : "r"(addr));
}
__device__ __forceinline__ void ldsm_x4_trans(uint32_t* r, uint32_t addr) {
    asm volatile("ldmatrix.sync.aligned.m8n8.x4.trans.shared.b16 {%0,%1,%2,%3}, [%4];"
        : "=r"(r[0]), "=r"(r[1]), "=r"(r[2]), "=r"(r[3]) : "r"(addr));
}

__device__ __forceinline__ void mma16816(float* c, const uint32_t* a,
                                          uint32_t b0, uint32_t b1) {
    asm volatile(
        "mma.sync.aligned.m16n8k16.row.col.f32.f16.f16.f32 "
        "{%0,%1,%2,%3}, {%4,%5,%6,%7}, {%8,%9}, {%0,%1,%2,%3};"
        : "+f"(c[0]), "+f"(c[1]), "+f"(c[2]), "+f"(c[3])
        : "r"(a[0]), "r"(a[1]), "r"(a[2]), "r"(a[3]), "r"(b0), "r"(b1));
}

__device__ __forceinline__ uint32_t pack_f16(float a, float b) {
    __half2 p = __halves2half2(__float2half_rn(a), __float2half_rn(b));
    return *(uint32_t*)&p;
}

// ---------------------------------------------------------------------------
// Merged prologue: X + 4 weights -> fp16 rn (64B per thread), + RoPE table,
// + work-counter reset.
// ---------------------------------------------------------------------------
#define NX4 (M_*E_/4)    // 2^21
#define NW4 (E_*E_/4)    // 2^20
#define NCONV (NX4 + 4*NW4)
#define NCONV4 (NCONV/4)
#define NTAB (S_*64)

__global__ __launch_bounds__(256) void prologue_kernel(
    const float* __restrict__ X,
    const float* __restrict__ Wq, const float* __restrict__ Wk,
    const float* __restrict__ Wv, const float* __restrict__ Wo)
{
    int idx = blockIdx.x * 256 + threadIdx.x;
    if (idx == 0) g_work = 0;          // reset work-stealing counter
    if (idx < NCONV4) {
        int e = idx << 2;   // quad base
        const float* src;
        __half* dst;
        int off;
        if (e < NX4) {
            src = X; dst = g_Xh; off = e;
        } else {
            int t = e - NX4;
            int slot = t >> 20;
            off = t & (NW4 - 1);
            src = (slot == 0) ? Wq : (slot == 1) ? Wk : (slot == 2) ? Wv : Wo;
            dst = g_Wh + (size_t)slot * E_ * E_;
        }
        float4 v0 = ((const float4*)src)[off];
        float4 v1 = ((const float4*)src)[off + 1];
        float4 v2 = ((const float4*)src)[off + 2];
        float4 v3 = ((const float4*)src)[off + 3];
        uint4 h0, h1;
        h0.x = pack_f16(v0.x, v0.y); h0.y = pack_f16(v0.z, v0.w);
        h0.z = pack_f16(v1.x, v1.y); h0.w = pack_f16(v1.z, v1.w);
        h1.x = pack_f16(v2.x, v2.y); h1.y = pack_f16(v2.z, v2.w);
        h1.z = pack_f16(v3.x, v3.y); h1.w = pack_f16(v3.z, v3.w);
        ((uint4*)dst)[(off >> 1) + 0] = h0;
        ((uint4*)dst)[(off >> 1) + 1] = h1;
    } else {
        int t = idx - NCONV4;
        if (t < NTAB) {
            int p = t >> 6;
            int i = t & 63;
            float inv = powf(10000.0f, -(float)(2 * i) / 128.0f);
            float sn, cs;
            sincosf((float)p * inv, &sn, &cs);
            g_cos[t] = cs;
            g_sin[t] = sn;
        }
    }
}

// ---------------------------------------------------------------------------
// fp16 single-term GEMM (proven config, unchanged).
// MODE 0: qkv (A = Xh), fused RoPE epilogue (Q pre-scaled).
// MODE 1: oproj (A = g_Ah), writes fp32 out.
// Block tile 128x128, 8 warps (warp tile 32x64), K-chunk 64, 2-stage,
// 2 CTAs/SM. Non-persistent.
// ---------------------------------------------------------------------------
#define KCH 64
#define NKC (E_/KCH)          // 32
#define ROWB 144              // 64 fp16 = 128B + 16B pad
#define TILE_B (128*ROWB)     // 18432
#define STG_B  (2*TILE_B)     // 36864: Ah, Bh
#define GEMM_SMEM 73728
#define CS_STRIDE 132

template<int MODE>
__global__ __launch_bounds__(256, 2) void gemm_mma(
    float* __restrict__ Oout, const int* __restrict__ posids)
{
    extern __shared__ char gsm[];
    const uint32_t sb = smem_to_u32(gsm);

    const int tid  = threadIdx.x;
    const int lane = tid & 31;
    const int wid  = tid >> 5;
    const int warpM = wid & 3;
    const int warpN = wid >> 2;
    const int m0 = blockIdx.y * 128;
    const int n0 = blockIdx.x * 128;
    const int z  = (MODE == 0) ? blockIdx.z : 3;

    const __half* Ahg = (MODE == 0) ? g_Xh : g_Ah;
    const __half* Bhg = g_Wh + (size_t)z * E_ * E_;

    const int lrow = tid >> 3;          // 0..31 (row base, +32 per it)
    const int lp   = tid & 7;           // 16B chunk within 128B row

    float c[2][8][4];
#pragma unroll
    for (int i = 0; i < 2; i++)
#pragma unroll
        for (int j = 0; j < 8; j++)
#pragma unroll
            for (int q = 0; q < 4; q++) c[i][j][q] = 0.f;

    const uint32_t aRow = (uint32_t)(warpM * 32 + (lane & 15)) * ROWB + (uint32_t)(lane >> 4) * 16;
    const uint32_t bRow = (uint32_t)(warpN * 64 + (lane & 7) + ((lane >> 4) << 3)) * ROWB
                        + (uint32_t)((lane >> 3) & 1) * 16;

    auto load_stage = [&](int buf, int kc) {
        const uint32_t stg = sb + buf * STG_B;
#pragma unroll
        for (int it = 0; it < 4; it++) {
            int row = lrow + it * 32;
            const size_t gA = (size_t)(m0 + row) * E_ + kc * KCH + lp * 8;
            const size_t gB = (size_t)(n0 + row) * E_ + kc * KCH + lp * 8;
            const uint32_t so = (uint32_t)(row * ROWB + lp * 16);
            CP_ASYNC16(stg + 0 * TILE_B + so, Ahg + gA);
            CP_ASYNC16(stg + 1 * TILE_B + so, Bhg + gB);
        }
        CP_ASYNC_COMMIT();
    };

    load_stage(0, 0);

    for (int kc = 0; kc < NKC; kc++) {
        const int buf = kc & 1;
        CP_ASYNC_WAIT0();
        __syncthreads();
        if (kc + 1 < NKC) load_stage(buf ^ 1, kc + 1);

        const uint32_t stg = sb + buf * STG_B;
#pragma unroll
        for (int ks = 0; ks < 4; ks++) {
            uint32_t ah[2][4], bh[4][4];
#pragma unroll
            for (int mi = 0; mi < 2; mi++) {
                uint32_t aoff = stg + aRow + (uint32_t)mi * 16 * ROWB + (uint32_t)ks * 32;
                ldsm_x4(ah[mi], aoff + 0 * TILE_B);
            }
#pragma unroll
            for (int g = 0; g < 4; g++) {
                uint32_t boff = stg + bRow + (uint32_t)g * 16 * ROWB + (uint32_t)ks * 32;
                ldsm_x4(bh[g], boff + 1 * TILE_B);
            }
#pragma unroll
            for (int mi = 0; mi < 2; mi++) {
#pragma unroll
                for (int g = 0; g < 4; g++) {
#pragma unroll
                    for (int hh = 0; hh < 2; hh++) {
                        mma16816(c[mi][2 * g + hh], ah[mi],
                                 bh[g][2 * hh], bh[g][2 * hh + 1]);
                    }
                }
            }
        }
        __syncthreads();
    }

    const int rr = lane >> 2;
    const int ct = 2 * (lane & 3);

    if (MODE == 1) {
#pragma unroll
        for (int mi = 0; mi < 2; mi++) {
#pragma unroll
            for (int ni = 0; ni < 8; ni++) {
                int row = m0 + warpM * 32 + mi * 16 + rr;
                int col = n0 + warpN * 64 + ni * 8 + ct;
                *(float2*)&Oout[(size_t)row * E_ + col] =
                    make_float2(c[mi][ni][0], c[mi][ni][1]);
                *(float2*)&Oout[(size_t)(row + 8) * E_ + col] =
                    make_float2(c[mi][ni][2], c[mi][ni][3]);
            }
        }
        return;
    }

    // ---- MODE 0 fused epilogue: stage C in smem, RoPE pair exchange ----
    float* Cs = (float*)gsm;
#pragma unroll
    for (int mi = 0; mi < 2; mi++) {
#pragma unroll
        for (int ni = 0; ni < 8; ni++) {
            int r = warpM * 32 + mi * 16 + rr;
            int ccol = warpN * 64 + ni * 8 + ct;
            *(float2*)&Cs[r * CS_STRIDE + ccol] =
                make_float2(c[mi][ni][0], c[mi][ni][1]);
            *(float2*)&Cs[(r + 8) * CS_STRIDE + ccol] =
                make_float2(c[mi][ni][2], c[mi][ni][3]);
        }
    }
    __syncthreads();

    const int headi = n0 >> 7;
    __half* Out = (z == 0) ? g_Qh : (z == 1) ? g_Kh : g_Vh;
    const float qsc = (z == 0) ? ASCALE : 1.0f;   // fold 1/sqrt(D) into Q

#pragma unroll
    for (int e = 0; e < 16; e++) {
        int idx = e * 256 + tid;
        int row = idx >> 5;
        int i2  = (idx & 31) << 1;
        int m = m0 + row;
        int bb = m >> 11, ss = m & (S_ - 1);
        size_t gbase = (((size_t)(bb * H_ + headi)) * S_ + ss) * D_;
        float2 xlo = *(float2*)&Cs[row * CS_STRIDE + i2];
        float2 xhi = *(float2*)&Cs[row * CS_STRIDE + i2 + 64];
        float o1x, o1y, o2x, o2y;
        if (z < 2) {
            int p = posids[bb * S_ + ss];
            float2 cs2 = *(float2*)&g_cos[p * 64 + i2];
            float2 sn2 = *(float2*)&g_sin[p * 64 + i2];
            o1x = (xlo.x * cs2.x - xhi.x * sn2.x) * qsc;
            o1y = (xlo.y * cs2.y - xhi.y * sn2.y) * qsc;
            o2x = (xhi.x * cs2.x + xlo.x * sn2.x) * qsc;
            o2y = (xhi.y * cs2.y + xlo.y * sn2.y) * qsc;
        } else {
            o1x = xlo.x; o1y = xlo.y; o2x = xhi.x; o2y = xhi.y;
        }
        *(uint32_t*)&Out[gbase + i2]      = pack_f16(o1x, o1y);
        *(uint32_t*)&Out[gbase + 64 + i2] = pack_f16(o2x, o2y);
    }
}

// ---------------------------------------------------------------------------
// Causal flash attention, fp16 single-term, PERSISTENT with LPT work-stealing.
// 296 CTAs (2/SM) pull items (qt,h,b) longest-first from a global counter.
// Per-item math identical to round-16 (deferred-l softmax, exp2).
// ---------------------------------------------------------------------------
#define AROW 272                 // 128 fp16 = 256B + 16B pad
#define QTILE_B (128*AROW)       // 34816
#define KVTILE  (64*AROW)        // 17408
#define AQ_H 0
#define KV_BASE QTILE_B          // 34816
#define KVSTG (2*KVTILE)         // KH, VH = 34816
#define KV_KH 0
#define KV_VH KVTILE
#define ATTN_SMEM (KV_BASE + 2*KVSTG)  // 104448 -> 2 CTAs/SM

__global__ __launch_bounds__(256, 2) void attn_mma()
{
    extern __shared__ char asm_[];
    const uint32_t sb = smem_to_u32(asm_);
    __shared__ int s_item;

    const int tid  = threadIdx.x;
    const int lane = tid & 31;
    const int warp = tid >> 5;

    const uint32_t aRow = (uint32_t)(warp * 16 + (lane & 15)) * AROW
                        + (uint32_t)(lane >> 4) * 16;
    const uint32_t bRow = (uint32_t)((lane & 7) + ((lane >> 4) << 3)) * AROW
                        + (uint32_t)((lane >> 3) & 1) * 16;
    const uint32_t vRow = (uint32_t)(lane & 15) * AROW
                        + (uint32_t)(lane >> 4) * 16;
    const int t2 = 2 * (lane & 3);

    for (;;) {
        if (tid == 0) s_item = (int)atomicAdd(&g_work, 1u);
        __syncthreads();           // broadcast item; also fences prior item's smem reads
        const int item = s_item;
        if (item >= N_ITEMS) return;

        // LPT order: largest qt first
        const int qt = 15 - (item >> 5);
        const int hb = item & 31;
        const int h  = hb & 15;
        const int b  = hb >> 4;

        const size_t headoff = (((size_t)(b * H_ + h)) * S_) * D_;
        const __half* Qh = g_Qh + headoff;
        const __half* Kh = g_Kh + headoff;
        const __half* Vh = g_Vh + headoff;

        // Q tile: 128 x 128 fp16
#pragma unroll
        for (int it = 0; it < 8; it++) {
            int lin = it * 256 + tid;
            int row = lin >> 4;
            int ch  = lin & 15;
            const size_t src = (size_t)(qt * 128 + row) * D_ + ch * 8;
            uint32_t dst = (uint32_t)(row * AROW + ch * 16);
            CP_ASYNC16(sb + AQ_H + dst, Qh + src);
        }
        CP_ASYNC_COMMIT();

        auto load_kv = [&](int bufi, int kt) {
            const uint32_t stg = sb + KV_BASE + bufi * KVSTG;
#pragma unroll
            for (int it = 0; it < 4; it++) {
                int lin = it * 256 + tid;
                int row = lin >> 4;
                int ch  = lin & 15;
                const size_t src = (size_t)(kt * 64 + row) * D_ + ch * 8;
                uint32_t dst = (uint32_t)(row * AROW + ch * 16);
                CP_ASYNC16(stg + KV_KH + dst, Kh + src);
                CP_ASYNC16(stg + KV_VH + dst, Vh + src);
            }
            CP_ASYNC_COMMIT();
        };

        load_kv(0, 0);
        CP_ASYNC_WAIT0();
        __syncthreads();

        float m0r = -INFINITY, m1r = -INFINITY;
        float l0r = 0.f, l1r = 0.f;    // per-thread partials (deferred reduce)
        float co[16][4];
#pragma unroll
        for (int j = 0; j < 16; j++)
#pragma unroll
            for (int q = 0; q < 4; q++) co[j][q] = 0.f;

        const int qrow0 = qt * 128 + warp * 16 + (lane >> 2);
        const int qrow1 = qrow0 + 8;
        const int nkt = 2 * qt + 2;

        for (int kt = 0; kt < nkt; kt++) {
            const int bufi = kt & 1;
            if (kt + 1 < nkt) load_kv(bufi ^ 1, kt + 1);
            const uint32_t kvs = sb + KV_BASE + bufi * KVSTG;

            // --- S = Q K^T (single term), scores already scaled ---
            float s[8][4];
#pragma unroll
            for (int j = 0; j < 8; j++)
#pragma unroll
                for (int q = 0; q < 4; q++) s[j][q] = 0.f;

#pragma unroll
            for (int kd = 0; kd < 8; kd++) {
                uint32_t qh_[4];
                ldsm_x4(qh_, sb + AQ_H + aRow + kd * 32);
#pragma unroll
                for (int g = 0; g < 4; g++) {
                    uint32_t kbh[4];
                    uint32_t boff = bRow + (uint32_t)g * 16 * AROW + (uint32_t)kd * 32;
                    ldsm_x4(kbh, kvs + KV_KH + boff);
#pragma unroll
                    for (int hh = 0; hh < 2; hh++) {
                        mma16816(s[2 * g + hh], qh_, kbh[2 * hh], kbh[2 * hh + 1]);
                    }
                }
            }

            // --- causal mask ---
            if (kt >= 2 * qt) {
                const int kbase = kt * 64 + 2 * (lane & 3);
#pragma unroll
                for (int j = 0; j < 8; j++) {
                    int k0 = kbase + 8 * j;
                    if (k0 > qrow0)     s[j][0] = -INFINITY;
                    if (k0 + 1 > qrow0) s[j][1] = -INFINITY;
                    if (k0 > qrow1)     s[j][2] = -INFINITY;
                    if (k0 + 1 > qrow1) s[j][3] = -INFINITY;
                }
            }

            // --- online softmax: max quad-consistent; sum deferred ---
            float mx0 = s[0][0], mx1 = s[0][2];
#pragma unroll
            for (int j = 0; j < 8; j++) {
                mx0 = fmaxf(mx0, fmaxf(s[j][0], s[j][1]));
                mx1 = fmaxf(mx1, fmaxf(s[j][2], s[j][3]));
            }
            mx0 = fmaxf(mx0, __shfl_xor_sync(0xffffffffu, mx0, 1));
            mx0 = fmaxf(mx0, __shfl_xor_sync(0xffffffffu, mx0, 2));
            mx1 = fmaxf(mx1, __shfl_xor_sync(0xffffffffu, mx1, 1));
            mx1 = fmaxf(mx1, __shfl_xor_sync(0xffffffffu, mx1, 2));

            float mn0 = fmaxf(m0r, mx0), mn1 = fmaxf(m1r, mx1);
            float corr0 = exp2f((m0r - mn0) * LOG2E);
            float corr1 = exp2f((m1r - mn1) * LOG2E);
            m0r = mn0; m1r = mn1;
            const float b0 = mn0 * LOG2E;
            const float b1 = mn1 * LOG2E;

            float rs0 = 0.f, rs1 = 0.f;
#pragma unroll
            for (int j = 0; j < 8; j++) {
                s[j][0] = exp2f(fmaf(s[j][0], LOG2E, -b0));
                s[j][1] = exp2f(fmaf(s[j][1], LOG2E, -b0));
                s[j][2] = exp2f(fmaf(s[j][2], LOG2E, -b1));
                s[j][3] = exp2f(fmaf(s[j][3], LOG2E, -b1));
                rs0 += s[j][0] + s[j][1];
                rs1 += s[j][2] + s[j][3];
            }
            l0r = l0r * corr0 + rs0;
            l1r = l1r * corr1 + rs1;

#pragma unroll
            for (int j = 0; j < 16; j++) {
                co[j][0] *= corr0; co[j][1] *= corr0;
                co[j][2] *= corr1; co[j][3] *= corr1;
            }

            // --- O += P V (single term) ---
#pragma unroll
            for (int ks = 0; ks < 4; ks++) {
                float* cA = s[2 * ks];
                float* cB = s[2 * ks + 1];
                uint32_t ph[4];
                ph[0] = pack_f16(cA[0], cA[1]);
                ph[1] = pack_f16(cA[2], cA[3]);
                ph[2] = pack_f16(cB[0], cB[1]);
                ph[3] = pack_f16(cB[2], cB[3]);
#pragma unroll
                for (int dd = 0; dd < 8; dd++) {
                    uint32_t vh_[4];
                    uint32_t voff = vRow + (uint32_t)ks * 16 * AROW + (uint32_t)dd * 32;
                    ldsm_x4_trans(vh_, kvs + KV_VH + voff);
                    mma16816(co[2 * dd],     ph, vh_[0], vh_[1]);
                    mma16816(co[2 * dd + 1], ph, vh_[2], vh_[3]);
                }
            }

            if (kt + 1 < nkt) CP_ASYNC_WAIT0();
            __syncthreads();   // all smem reads of bufi done (also fences item end)
        }

        // --- epilogue: reduce l across quad once, normalize, write A ---
        float L0 = l0r, L1 = l1r;
        L0 += __shfl_xor_sync(0xffffffffu, L0, 1);
        L0 += __shfl_xor_sync(0xffffffffu, L0, 2);
        L1 += __shfl_xor_sync(0xffffffffu, L1, 1);
        L1 += __shfl_xor_sync(0xffffffffu, L1, 2);
        const float invl0 = 1.f / L0;
        const float invl1 = 1.f / L1;
        const size_t rowA0 = ((size_t)(b * S_ + qrow0)) * E_ + h * D_;
        const size_t rowA1 = ((size_t)(b * S_ + qrow1)) * E_ + h * D_;
#pragma unroll
        for (int j = 0; j < 16; j++) {
            int col = 8 * j + t2;
            float a0 = co[j][0] * invl0, a1 = co[j][1] * invl0;
            float a2 = co[j][2] * invl1, a3 = co[j][3] * invl1;
            *(uint32_t*)&g_Ah[rowA0 + col] = pack_f16(a0, a1);
            *(uint32_t*)&g_Ah[rowA1 + col] = pack_f16(a2, a3);
        }
    }
}

// ---------------------------------------------------------------------------
extern "C" void kernel_launch(void* const* d_in, const int* in_sizes, int n_in,
                              void* d_out, int out_size)
{
    const float* hidden = (const float*)d_in[0];
    const int*   posids = (const int*)d_in[2];
    const float* Wq     = (const float*)d_in[3];
    const float* Wk     = (const float*)d_in[4];
    const float* Wv     = (const float*)d_in[5];
    const float* Wo     = (const float*)d_in[6];
    float*       out    = (float*)d_out;

    cudaFuncSetAttribute(gemm_mma<0>,
                         cudaFuncAttributeMaxDynamicSharedMemorySize, GEMM_SMEM);
    cudaFuncSetAttribute(gemm_mma<1>,
                         cudaFuncAttributeMaxDynamicSharedMemorySize, GEMM_SMEM);
    cudaFuncSetAttribute(attn_mma,
                         cudaFuncAttributeMaxDynamicSharedMemorySize, ATTN_SMEM);

    int smCount = 148;
    cudaDeviceGetAttribute(&smCount, cudaDevAttrMultiProcessorCount, 0);

    // 1) merged prologue: fp16 converts + RoPE table + counter reset
    {
        int total = NCONV4 + NTAB;
        prologue_kernel<<<(total + 255) / 256, 256>>>(hidden, Wq, Wk, Wv, Wo);
    }
    // 2) QKV projections + fused RoPE epilogue
    {
        dim3 grid(E_ / 128, M_ / 128, 3);
        gemm_mma<0><<<grid, 256, GEMM_SMEM>>>(nullptr, posids);
    }
    // 3) causal flash attention (persistent, LPT work-stealing) -> g_Ah
    attn_mma<<<2 * smCount, 256, ATTN_SMEM>>>();
    // 4) output projection -> d_out
    {
        dim3 grid(E_ / 128, M_ / 128);
        gemm_mma<1><<<grid, 256, GEMM_SMEM>>>(out, nullptr);
    }
}